// round 1
// baseline (speedup 1.0000x reference)
#include <cuda_runtime.h>
#include <cstdint>

#define NN 100000
#define EE 1600000
#define IN_F 128
#define HID_F 256
#define OUT_F 47

// ---------------- scratch (static device allocations; no cudaMalloc) -------
__device__ float g_agg[(size_t)NN * HID_F];   // aggregation buffer (reused)
__device__ float g_h  [(size_t)NN * HID_F];   // relu(layer0 out)
__device__ float g_h2 [(size_t)NN * HID_F];   // relu(h_out)
__device__ float g_t2 [(size_t)NN * OUT_F];   // h2 @ Wl2
__device__ int   g_count [NN];
__device__ float g_invdeg[NN];
__device__ int   g_rowptr[NN + 1];
__device__ int   g_cursor[NN];
__device__ int   g_csrsrc[EE];
__device__ int   g_bsums [128];
__device__ int   g_is64;

// ---------------- edge dtype detection -------------------------------------
// int64 values < 2^31 have zero upper 32-bit words; int32 random node ids
// (uniform in [0,1e5)) are ~never 0 for 256 consecutive odd words.
__global__ void k_detect(const int* ei_raw) {
    if (threadIdx.x == 0 && blockIdx.x == 0) {
        int is64 = 1;
        for (int i = 0; i < 256; i++) {
            if (ei_raw[2 * i + 1] != 0) { is64 = 0; break; }
        }
        g_is64 = is64;
    }
}

__device__ __forceinline__ int load_edge(const void* ei, long long idx, int is64) {
    if (is64) return (int)((const long long*)ei)[idx];
    return ((const int*)ei)[idx];
}

// ---------------- CSR build -------------------------------------------------
__global__ void k_hist(const void* ei) {
    int e = blockIdx.x * blockDim.x + threadIdx.x;
    if (e < EE) {
        int d = load_edge(ei, (long long)EE + e, g_is64);
        atomicAdd(&g_count[d], 1);
    }
}

__global__ void k_scan1() {
    __shared__ int sh[1024];
    int i = blockIdx.x * 1024 + threadIdx.x;
    int v = (i < NN) ? g_count[i] : 0;
    sh[threadIdx.x] = v;
    __syncthreads();
    for (int off = 1; off < 1024; off <<= 1) {
        int t = (threadIdx.x >= off) ? sh[threadIdx.x - off] : 0;
        __syncthreads();
        sh[threadIdx.x] += t;
        __syncthreads();
    }
    if (i < NN) g_rowptr[i] = sh[threadIdx.x] - v;  // exclusive
    if (threadIdx.x == 1023) g_bsums[blockIdx.x] = sh[1023];
}

__global__ void k_scan2(int nb) {
    if (threadIdx.x == 0 && blockIdx.x == 0) {
        int run = 0;
        for (int b = 0; b < nb; b++) { int t = g_bsums[b]; g_bsums[b] = run; run += t; }
    }
}

__global__ void k_scan3() {
    int i = blockIdx.x * 1024 + threadIdx.x;
    if (i < NN) {
        int r = g_rowptr[i] + g_bsums[blockIdx.x];
        g_rowptr[i] = r;
        g_cursor[i] = r;
        g_invdeg[i] = 1.0f / (float)max(g_count[i], 1);
    }
    if (i == 0) g_rowptr[NN] = EE;
}

__global__ void k_scatter(const void* ei) {
    int e = blockIdx.x * blockDim.x + threadIdx.x;
    if (e < EE) {
        int is64 = g_is64;
        int d = load_edge(ei, (long long)EE + e, is64);
        int s = load_edge(ei, e, is64);
        int p = atomicAdd(&g_cursor[d], 1);
        g_csrsrc[p] = s;
    }
}

// ---------------- mean aggregation (CSR gather), vector widths --------------
// One warp per destination node. NV float4 per lane -> width = 128*NV floats.
template <int NV>
__global__ void k_agg_vec(const float* __restrict__ X, float* __restrict__ Out) {
    int w = (blockIdx.x * blockDim.x + threadIdx.x) >> 5;
    int lane = threadIdx.x & 31;
    if (w >= NN) return;
    int beg = g_rowptr[w], end = g_rowptr[w + 1];
    const int Wd = NV * 128;
    float4 acc[NV];
#pragma unroll
    for (int v = 0; v < NV; v++) acc[v] = make_float4(0.f, 0.f, 0.f, 0.f);
    for (int e = beg; e < end; e++) {
        int s = g_csrsrc[e];
        const float4* row = (const float4*)(X + (size_t)s * Wd);
#pragma unroll
        for (int v = 0; v < NV; v++) {
            float4 t = row[lane + 32 * v];
            acc[v].x += t.x; acc[v].y += t.y; acc[v].z += t.z; acc[v].w += t.w;
        }
    }
    float inv = g_invdeg[w];
    float4* orow = (float4*)(Out + (size_t)w * Wd);
#pragma unroll
    for (int v = 0; v < NV; v++) {
        acc[v].x *= inv; acc[v].y *= inv; acc[v].z *= inv; acc[v].w *= inv;
        orow[lane + 32 * v] = acc[v];
    }
}

// width-47 scalar aggregation (one warp per node; lane covers col lane and lane+32)
__global__ void k_agg47(const float* __restrict__ X, float* __restrict__ Out) {
    int w = (blockIdx.x * blockDim.x + threadIdx.x) >> 5;
    int lane = threadIdx.x & 31;
    if (w >= NN) return;
    int beg = g_rowptr[w], end = g_rowptr[w + 1];
    float a0 = 0.f, a1 = 0.f;
    for (int e = beg; e < end; e++) {
        int s = g_csrsrc[e];
        const float* row = X + (size_t)s * OUT_F;
        a0 += row[lane];
        if (lane < OUT_F - 32) a1 += row[lane + 32];
    }
    float inv = g_invdeg[w];
    float* orow = Out + (size_t)w * OUT_F;
    orow[lane] = a0 * inv;
    if (lane < OUT_F - 32) orow[lane + 32] = a1 * inv;
}

// ---------------- fp32 register-blocked GEMM -------------------------------
// C[M,NO] = A1@W1 (+ A2@W2) + bias (+ Dadd); optional pre-activation output
// and ReLU. BM=128, BK=8, TM=8; 256 threads; BN/TN selects 128/8 or 64/4.
template <int BN, int TN, bool DUAL, bool BIAS, bool RELU, bool WRITE_PRE, bool ADD_D>
__global__ void __launch_bounds__(256)
k_gemm(const float* __restrict__ A1, const float* __restrict__ W1, int K1,
       const float* __restrict__ A2, const float* __restrict__ W2, int K2,
       const float* __restrict__ bias, const float* __restrict__ Dadd,
       float* __restrict__ Cout, float* __restrict__ Cpre, int M, int NO) {
    constexpr int BM = 128, BK = 8, TM = 8;
    constexpr int THREADS = 16 * (BN / TN);
    static_assert(THREADS == 256, "thread count");
    __shared__ float As[BK][BM];
    __shared__ float Bs[BK][BN];

    int tid = threadIdx.x;
    int rowBlk = blockIdx.x * BM;
    int colBlk = blockIdx.y * BN;
    int tcol = tid % (BN / TN);
    int trow = tid / (BN / TN);

    float acc[TM][TN];
#pragma unroll
    for (int i = 0; i < TM; i++)
#pragma unroll
        for (int j = 0; j < TN; j++) acc[i][j] = 0.f;

    const int KT = DUAL ? (K1 + K2) : K1;
    for (int kk = 0; kk < KT; kk += BK) {
        const float* A; const float* Wm; int kO, ldA;
        if (DUAL && kk >= K1) { A = A2; Wm = W2; kO = kk - K1; ldA = K2; }
        else                  { A = A1; Wm = W1; kO = kk;      ldA = K1; }
        // A tile: 128x8 = 1024 floats = 256 x float4 (transposed store)
        {
            int r = tid >> 1;
            int c4 = (tid & 1) * 4;
            int gr = rowBlk + r;
            float4 v = make_float4(0.f, 0.f, 0.f, 0.f);
            if (gr < M) v = *(const float4*)(A + (size_t)gr * ldA + kO + c4);
            As[c4 + 0][r] = v.x; As[c4 + 1][r] = v.y;
            As[c4 + 2][r] = v.z; As[c4 + 3][r] = v.w;
        }
        // B tile: 8 x BN, scalar guarded loads
        for (int i = tid; i < BK * BN; i += THREADS) {
            int r = i / BN, c = i % BN;
            int gc = colBlk + c;
            Bs[r][c] = (gc < NO) ? Wm[(size_t)(kO + r) * NO + gc] : 0.f;
        }
        __syncthreads();
#pragma unroll
        for (int k = 0; k < BK; k++) {
            float a[TM], b[TN];
#pragma unroll
            for (int i = 0; i < TM; i++) a[i] = As[k][trow * TM + i];
#pragma unroll
            for (int j = 0; j < TN; j++) b[j] = Bs[k][tcol * TN + j];
#pragma unroll
            for (int i = 0; i < TM; i++)
#pragma unroll
                for (int j = 0; j < TN; j++) acc[i][j] = fmaf(a[i], b[j], acc[i][j]);
        }
        __syncthreads();
    }

#pragma unroll
    for (int i = 0; i < TM; i++) {
        int gr = rowBlk + trow * TM + i;
        if (gr < M) {
#pragma unroll
            for (int j = 0; j < TN; j++) {
                int gc = colBlk + tcol * TN + j;
                if (gc < NO) {
                    float v = acc[i][j];
                    if (BIAS)  v += bias[gc];
                    if (ADD_D) v += Dadd[(size_t)gr * NO + gc];
                    if (WRITE_PRE) Cpre[(size_t)gr * NO + gc] = v;
                    Cout[(size_t)gr * NO + gc] = RELU ? fmaxf(v, 0.f) : v;
                }
            }
        }
    }
}

// ---------------- launch ----------------------------------------------------
extern "C" void kernel_launch(void* const* d_in, const int* in_sizes, int n_in,
                              void* d_out, int out_size) {
    const float* x   = (const float*)d_in[0];
    const void*  ei  = d_in[1];
    const float* Wl0 = (const float*)d_in[2];
    const float* bl0 = (const float*)d_in[3];
    const float* Wr0 = (const float*)d_in[4];
    const float* Wl1 = (const float*)d_in[5];
    const float* bl1 = (const float*)d_in[6];
    const float* Wr1 = (const float*)d_in[7];
    const float* Wl2 = (const float*)d_in[8];
    const float* bl2 = (const float*)d_in[9];
    const float* Wr2 = (const float*)d_in[10];

    float* out  = (float*)d_out;                       // [N,47]
    float* hout = out + (size_t)NN * OUT_F;            // [N,256] pre-ReLU hidden

    float *p_agg, *p_h, *p_h2, *p_t2;
    int* p_count;
    cudaGetSymbolAddress((void**)&p_agg,   g_agg);
    cudaGetSymbolAddress((void**)&p_h,     g_h);
    cudaGetSymbolAddress((void**)&p_h2,    g_h2);
    cudaGetSymbolAddress((void**)&p_t2,    g_t2);
    cudaGetSymbolAddress((void**)&p_count, g_count);

    const int NB_SCAN = (NN + 1023) / 1024;            // 98

    // ---- CSR build (deg shared by all 3 layers) ----
    cudaMemsetAsync(p_count, 0, NN * sizeof(int));
    k_detect<<<1, 32>>>((const int*)ei);
    k_hist<<<(EE + 255) / 256, 256>>>(ei);
    k_scan1<<<NB_SCAN, 1024>>>();
    k_scan2<<<1, 32>>>(NB_SCAN);
    k_scan3<<<NB_SCAN, 1024>>>();
    k_scatter<<<(EE + 255) / 256, 256>>>(ei);

    const int AGG_BLKS = (NN + 7) / 8;                 // 8 warps/block
    dim3 gemm256(782, 2);                               // 128-row tiles, NO=256
    dim3 gemm47(782, 1);                                // NO=47 (BN=64)

    // ---- layer 0: agg(x) @ Wl0 + bl0 + x @ Wr0, relu -> g_h ----
    k_agg_vec<1><<<AGG_BLKS, 256>>>(x, p_agg);
    k_gemm<128, 8, true, true, true, false, false><<<gemm256, 256>>>(
        p_agg, Wl0, IN_F, x, Wr0, IN_F, bl0, nullptr, p_h, nullptr, NN, HID_F);

    // ---- layer 1: agg(h) @ Wl1 + bl1 + h @ Wr1 -> hout (pre), relu -> g_h2 ----
    k_agg_vec<2><<<AGG_BLKS, 256>>>(p_h, p_agg);
    k_gemm<128, 8, true, true, true, true, false><<<gemm256, 256>>>(
        p_agg, Wl1, HID_F, p_h, Wr1, HID_F, bl1, nullptr, p_h2, hout, NN, HID_F);

    // ---- layer 2 (transform-then-aggregate, width 47) ----
    // t2 = h2 @ Wl2
    k_gemm<64, 4, false, false, false, false, false><<<gemm47, 256>>>(
        p_h2, Wl2, HID_F, nullptr, nullptr, 0, nullptr, nullptr, p_t2, nullptr, NN, OUT_F);
    // agg2 = mean-agg(t2)
    k_agg47<<<AGG_BLKS, 256>>>(p_t2, p_agg);
    // out = agg2 + bl2 + h2 @ Wr2
    k_gemm<64, 4, false, true, false, false, true><<<gemm47, 256>>>(
        p_h2, Wr2, HID_F, nullptr, nullptr, 0, bl2, p_agg, out, nullptr, NN, OUT_F);
}

// round 3
// speedup vs baseline: 1.9680x; 1.9680x over previous
#include <cuda_runtime.h>
#include <cuda_bf16.h>
#include <cstdint>

#define NN 100000
#define EE 1600000
#define IN_F 128
#define HID_F 256
#define OUT_F 47
#define T2S 48

// ---------------- scratch ---------------------------------------------------
__device__ float g_agg[(size_t)NN * HID_F];
__device__ float g_h  [(size_t)NN * HID_F];
__device__ float g_h2 [(size_t)NN * HID_F];
__device__ float g_t2 [(size_t)NN * T2S];
__device__ int   g_count [NN];
__device__ float g_invdeg[NN];
__device__ int   g_rowptr[NN + 1];
__device__ int   g_cursor[NN];
__device__ int   g_csrsrc[EE];
__device__ int   g_bsums [128];
__device__ int   g_is64;

// weight tables, bf16 hi/lo, transposed to [N,K] row-major
// offsets: B0l 0 (256x128), B0r 32768, B1l 65536 (256x256), B1r 131072,
//          B2l 196608 (64x256), B2r 212992 ; total 229376
#define WB_TOTAL 229376
__device__ __nv_bfloat16 g_wbhi[WB_TOTAL];
__device__ __nv_bfloat16 g_wblo[WB_TOTAL];

// ---------------- prep ------------------------------------------------------
__global__ void k_prep(const int* ei_raw,
                       const float* Wl0, const float* Wr0,
                       const float* Wl1, const float* Wr1,
                       const float* Wl2, const float* Wr2) {
    int idx = blockIdx.x * blockDim.x + threadIdx.x;
    if (idx < NN) g_count[idx] = 0;
    if (idx == 0) {
        int is64 = 1;
        for (int i = 0; i < 256; i++)
            if (ei_raw[2 * i + 1] != 0) { is64 = 0; break; }
        g_is64 = is64;
    }
    if (idx < WB_TOTAL) {
        float w;
        if (idx < 32768)       { int l = idx;          int n = l >> 7, k = l & 127; w = Wl0[k * 256 + n]; }
        else if (idx < 65536)  { int l = idx - 32768;  int n = l >> 7, k = l & 127; w = Wr0[k * 256 + n]; }
        else if (idx < 131072) { int l = idx - 65536;  int n = l >> 8, k = l & 255; w = Wl1[k * 256 + n]; }
        else if (idx < 196608) { int l = idx - 131072; int n = l >> 8, k = l & 255; w = Wr1[k * 256 + n]; }
        else if (idx < 212992) { int l = idx - 196608; int n = l >> 8, k = l & 255; w = (n < OUT_F) ? Wl2[k * OUT_F + n] : 0.f; }
        else                   { int l = idx - 212992; int n = l >> 8, k = l & 255; w = (n < OUT_F) ? Wr2[k * OUT_F + n] : 0.f; }
        __nv_bfloat16 hi = __float2bfloat16(w);
        __nv_bfloat16 lo = __float2bfloat16(w - __bfloat162float(hi));
        g_wbhi[idx] = hi;
        g_wblo[idx] = lo;
    }
}

// ---------------- CSR build -------------------------------------------------
__device__ __forceinline__ int load_edge(const void* ei, long long idx, int is64) {
    if (is64) return (int)((const long long*)ei)[idx];
    return ((const int*)ei)[idx];
}

__global__ void k_hist(const void* ei) {
    int e = blockIdx.x * blockDim.x + threadIdx.x;
    if (e < EE) {
        int d = load_edge(ei, (long long)EE + e, g_is64);
        atomicAdd(&g_count[d], 1);
    }
}

__global__ void k_scan1() {
    __shared__ int sh[1024];
    int i = blockIdx.x * 1024 + threadIdx.x;
    int v = (i < NN) ? g_count[i] : 0;
    sh[threadIdx.x] = v;
    __syncthreads();
    for (int off = 1; off < 1024; off <<= 1) {
        int t = (threadIdx.x >= off) ? sh[threadIdx.x - off] : 0;
        __syncthreads();
        sh[threadIdx.x] += t;
        __syncthreads();
    }
    if (i < NN) g_rowptr[i] = sh[threadIdx.x] - v;
    if (threadIdx.x == 1023) g_bsums[blockIdx.x] = sh[1023];
}

__global__ void k_scan23() {
    __shared__ int base;
    if (threadIdx.x == 0) {
        int run = 0;
        for (int b = 0; b < (int)blockIdx.x; b++) run += g_bsums[b];
        base = run;
    }
    __syncthreads();
    int i = blockIdx.x * 1024 + threadIdx.x;
    if (i < NN) {
        int r = g_rowptr[i] + base;
        g_rowptr[i] = r;
        g_cursor[i] = r;
        g_invdeg[i] = 1.0f / (float)max(g_count[i], 1);
    }
    if (i == 0) g_rowptr[NN] = EE;
}

__global__ void k_scatter(const void* ei) {
    int e = blockIdx.x * blockDim.x + threadIdx.x;
    if (e < EE) {
        int is64 = g_is64;
        int d = load_edge(ei, (long long)EE + e, is64);
        int s = load_edge(ei, e, is64);
        int p = atomicAdd(&g_cursor[d], 1);
        g_csrsrc[p] = s;
    }
}

// ---------------- mean aggregation ------------------------------------------
template <int NV>
__global__ void k_agg_vec(const float* __restrict__ X, float* __restrict__ Out) {
    int w = (blockIdx.x * blockDim.x + threadIdx.x) >> 5;
    int lane = threadIdx.x & 31;
    if (w >= NN) return;
    int beg = g_rowptr[w], end = g_rowptr[w + 1];
    const int Wd = NV * 128;
    float4 acc[NV];
#pragma unroll
    for (int v = 0; v < NV; v++) acc[v] = make_float4(0.f, 0.f, 0.f, 0.f);
    for (int e = beg; e < end; e++) {
        int s = g_csrsrc[e];
        const float4* row = (const float4*)(X + (size_t)s * Wd);
#pragma unroll
        for (int v = 0; v < NV; v++) {
            float4 t = row[lane + 32 * v];
            acc[v].x += t.x; acc[v].y += t.y; acc[v].z += t.z; acc[v].w += t.w;
        }
    }
    float inv = g_invdeg[w];
    float4* orow = (float4*)(Out + (size_t)w * Wd);
#pragma unroll
    for (int v = 0; v < NV; v++) {
        acc[v].x *= inv; acc[v].y *= inv; acc[v].z *= inv; acc[v].w *= inv;
        orow[lane + 32 * v] = acc[v];
    }
}

__global__ void k_agg47(const float* __restrict__ X, float* __restrict__ Out) {
    int w = (blockIdx.x * blockDim.x + threadIdx.x) >> 5;
    int lane = threadIdx.x & 31;
    if (w >= NN) return;
    int beg = g_rowptr[w], end = g_rowptr[w + 1];
    float a0 = 0.f, a1 = 0.f;
    for (int e = beg; e < end; e++) {
        int s = g_csrsrc[e];
        const float* row = X + (size_t)s * T2S;
        a0 += row[lane];
        if (lane < OUT_F - 32) a1 += row[lane + 32];
    }
    float inv = g_invdeg[w];
    float* orow = Out + (size_t)w * T2S;
    orow[lane] = a0 * inv;
    if (lane < OUT_F - 32) orow[lane + 32] = a1 * inv;
}

// ---------------- bf16-split GEMM via mma.sync (HMMA) -----------------------
// C[M,NW] = sum over segs of A@W, bf16 hi/lo 3-pass split, fp32 accumulate.
// BM=128 rows per CTA, BN cols per CTA (grid.y covers N). 8 warps, each warp
// computes 32 x (BN/2) via m16n8k16 fragments fed from padded smem.
__device__ __forceinline__ void mma16816(float* c, const uint32_t* a, const uint32_t* b) {
    asm volatile(
        "mma.sync.aligned.m16n8k16.row.col.f32.bf16.bf16.f32 "
        "{%0,%1,%2,%3}, {%4,%5,%6,%7}, {%8,%9}, {%0,%1,%2,%3};"
        : "+f"(c[0]), "+f"(c[1]), "+f"(c[2]), "+f"(c[3])
        : "r"(a[0]), "r"(a[1]), "r"(a[2]), "r"(a[3]), "r"(b[0]), "r"(b[1]));
}

template <int BN, bool DUAL, bool BIAS, bool RELU, bool WRITE_PRE, bool ADD_D>
__global__ void __launch_bounds__(256)
k_mma(const float* __restrict__ A1, int ldA1, int K1,
      const __nv_bfloat16* __restrict__ Bh1, const __nv_bfloat16* __restrict__ Bl1, int ldB1,
      const float* __restrict__ A2, int ldA2, int K2,
      const __nv_bfloat16* __restrict__ Bh2, const __nv_bfloat16* __restrict__ Bl2, int ldB2,
      const float* __restrict__ bias, const float* __restrict__ Dadd, int ldD,
      float* __restrict__ Cout, int ldC, int NW, float* __restrict__ Cpre, int M) {
    constexpr int ASTR = 40;            // padded smem strides (bf16 units)
    constexpr int BSTR = 40;
    constexpr int NT = BN / 16;         // n8 tiles per warp (warp covers BN/2 cols)
    __shared__ __nv_bfloat16 Asm[128 * ASTR];
    __shared__ __nv_bfloat16 Bsm[BN * BSTR];

    const int tid  = threadIdx.x;
    const int wid  = tid >> 5;
    const int lane = tid & 31;
    const int wm   = wid & 3;           // 4 warps along M
    const int wn   = wid >> 2;          // 2 warps along N
    const int gid  = lane >> 2;
    const int tig  = lane & 3;

    const int rowBase = blockIdx.x * 128;
    const int colBlk  = blockIdx.y * BN;

    float acc[2][NT][4];
#pragma unroll
    for (int mt = 0; mt < 2; mt++)
#pragma unroll
        for (int nt = 0; nt < NT; nt++)
#pragma unroll
            for (int j = 0; j < 4; j++) acc[mt][nt][j] = 0.f;

    const int NSEG = DUAL ? 2 : 1;
    for (int seg = 0; seg < NSEG; seg++) {
        const float* Ap = seg ? A2 : A1;
        const int ldA   = seg ? ldA2 : ldA1;
        const int Kseg  = seg ? K2 : K1;
        for (int pass = 0; pass < 3; pass++) {
            const __nv_bfloat16* Bt = (pass == 1) ? (seg ? Bl2 : Bl1)
                                                  : (seg ? Bh2 : Bh1);
            const int ldB = seg ? ldB2 : ldB1;
            const bool a_lo = (pass == 2);
            for (int k0 = 0; k0 < Kseg; k0 += 32) {
                __syncthreads();   // previous compute done before overwrite
                // ---- A tile: 128x32 fp32 -> bf16(hi|lo) ----
                {
                    int row = tid >> 1, ch = tid & 1;    // 256 = 128*2 slots
                    int gr = rowBase + row;
                    const float* src = Ap + (size_t)gr * ldA + k0 + ch * 16;
                    uint32_t pk[8];
                    if (gr < M) {
#pragma unroll
                        for (int q = 0; q < 4; q++) {
                            float4 v = ((const float4*)src)[q];
                            __nv_bfloat16 h0 = __float2bfloat16(v.x);
                            __nv_bfloat16 h1 = __float2bfloat16(v.y);
                            __nv_bfloat16 h2 = __float2bfloat16(v.z);
                            __nv_bfloat16 h3 = __float2bfloat16(v.w);
                            __nv_bfloat16 e0, e1, e2, e3;
                            if (a_lo) {
                                e0 = __float2bfloat16(v.x - __bfloat162float(h0));
                                e1 = __float2bfloat16(v.y - __bfloat162float(h1));
                                e2 = __float2bfloat16(v.z - __bfloat162float(h2));
                                e3 = __float2bfloat16(v.w - __bfloat162float(h3));
                            } else { e0 = h0; e1 = h1; e2 = h2; e3 = h3; }
                            pk[2 * q]     = ((uint32_t)__bfloat16_as_ushort(e1) << 16) | __bfloat16_as_ushort(e0);
                            pk[2 * q + 1] = ((uint32_t)__bfloat16_as_ushort(e3) << 16) | __bfloat16_as_ushort(e2);
                        }
                    } else {
#pragma unroll
                        for (int q = 0; q < 8; q++) pk[q] = 0u;
                    }
                    uint32_t* dst = (uint32_t*)(Asm + row * ASTR + ch * 16);
#pragma unroll
                    for (int q = 0; q < 8; q++) dst[q] = pk[q];
                }
                // ---- B tile: BN x 32 bf16 from split table ----
                for (int i = tid; i < BN * 2; i += 256) {
                    int row = i >> 1, ch = i & 1;
                    const uint4* src = (const uint4*)(Bt + (size_t)(colBlk + row) * ldB + k0 + ch * 16);
                    uint4 d0 = src[0], d1 = src[1];
                    uint4* dst = (uint4*)(Bsm + row * BSTR + ch * 16);
                    dst[0] = d0; dst[1] = d1;
                }
                __syncthreads();
                // ---- compute: two k16 halves ----
#pragma unroll
                for (int ks = 0; ks < 2; ks++) {
                    const int kb = ks * 16;
                    uint32_t a[2][4];
#pragma unroll
                    for (int mt = 0; mt < 2; mt++) {
                        int r0 = 32 * wm + mt * 16 + gid;
                        const uint32_t* ap = (const uint32_t*)(Asm + r0 * ASTR + kb);
                        a[mt][0] = ap[tig];
                        a[mt][2] = ap[tig + 4];
                        const uint32_t* ap8 = (const uint32_t*)(Asm + (r0 + 8) * ASTR + kb);
                        a[mt][1] = ap8[tig];
                        a[mt][3] = ap8[tig + 4];
                    }
                    uint32_t b[NT][2];
#pragma unroll
                    for (int nt = 0; nt < NT; nt++) {
                        int brow = wn * (8 * NT) + nt * 8 + gid;
                        const uint32_t* bp = (const uint32_t*)(Bsm + brow * BSTR + kb);
                        b[nt][0] = bp[tig];
                        b[nt][1] = bp[tig + 4];
                    }
#pragma unroll
                    for (int mt = 0; mt < 2; mt++)
#pragma unroll
                        for (int nt = 0; nt < NT; nt++)
                            mma16816(acc[mt][nt], a[mt], b[nt]);
                }
            }
        }
    }

    // ---- epilogue ----
#pragma unroll
    for (int mt = 0; mt < 2; mt++) {
        int r0 = rowBase + 32 * wm + mt * 16 + gid;
        int r1 = r0 + 8;
#pragma unroll
        for (int nt = 0; nt < NT; nt++) {
            int gc = colBlk + wn * (8 * NT) + nt * 8 + 2 * tig;
#pragma unroll
            for (int half = 0; half < 2; half++) {
                int rr = half ? r1 : r0;
                if (rr >= M) continue;
                float v0 = acc[mt][nt][half * 2 + 0];
                float v1 = acc[mt][nt][half * 2 + 1];
                if (BN == 128) {            // NW==256, no col guard
                    if (BIAS) { v0 += bias[gc]; v1 += bias[gc + 1]; }
                    float* pre = Cpre + (size_t)rr * ldC + gc;
                    if (WRITE_PRE) { pre[0] = v0; pre[1] = v1; }
                    if (RELU) { v0 = fmaxf(v0, 0.f); v1 = fmaxf(v1, 0.f); }
                    float2* o = (float2*)(Cout + (size_t)rr * ldC + gc);
                    *o = make_float2(v0, v1);
                } else {
                    if (gc < NW) {
                        float v = v0;
                        if (BIAS)  v += bias[gc];
                        if (ADD_D) v += Dadd[(size_t)rr * ldD + gc];
                        Cout[(size_t)rr * ldC + gc] = RELU ? fmaxf(v, 0.f) : v;
                    }
                    if (gc + 1 < NW) {
                        float v = v1;
                        if (BIAS)  v += bias[gc + 1];
                        if (ADD_D) v += Dadd[(size_t)rr * ldD + gc + 1];
                        Cout[(size_t)rr * ldC + gc + 1] = RELU ? fmaxf(v, 0.f) : v;
                    }
                }
            }
        }
    }
}

// ---------------- launch ----------------------------------------------------
extern "C" void kernel_launch(void* const* d_in, const int* in_sizes, int n_in,
                              void* d_out, int out_size) {
    const float* x   = (const float*)d_in[0];
    const void*  ei  = d_in[1];
    const float* Wl0 = (const float*)d_in[2];
    const float* bl0 = (const float*)d_in[3];
    const float* Wr0 = (const float*)d_in[4];
    const float* Wl1 = (const float*)d_in[5];
    const float* bl1 = (const float*)d_in[6];
    const float* Wr1 = (const float*)d_in[7];
    const float* Wl2 = (const float*)d_in[8];
    const float* bl2 = (const float*)d_in[9];
    const float* Wr2 = (const float*)d_in[10];

    float* out  = (float*)d_out;
    float* hout = out + (size_t)NN * OUT_F;

    float *p_agg, *p_h, *p_h2, *p_t2;
    __nv_bfloat16 *wbh, *wbl;
    cudaGetSymbolAddress((void**)&p_agg, g_agg);
    cudaGetSymbolAddress((void**)&p_h,   g_h);
    cudaGetSymbolAddress((void**)&p_h2,  g_h2);
    cudaGetSymbolAddress((void**)&p_t2,  g_t2);
    cudaGetSymbolAddress((void**)&wbh,   g_wbhi);
    cudaGetSymbolAddress((void**)&wbl,   g_wblo);

    const int MT = (NN + 127) / 128;               // 782
    const int AGG_BLKS = (NN + 7) / 8;

    // CSR build + weight split
    k_prep<<<(WB_TOTAL + 255) / 256, 256>>>((const int*)ei, Wl0, Wr0, Wl1, Wr1, Wl2, Wr2);
    k_hist<<<(EE + 255) / 256, 256>>>(ei);
    k_scan1<<<(NN + 1023) / 1024, 1024>>>();
    k_scan23<<<(NN + 1023) / 1024, 1024>>>();
    k_scatter<<<(EE + 255) / 256, 256>>>(ei);

    // layer 0: relu(agg(x)@Wl0 + bl0 + x@Wr0) -> g_h
    k_agg_vec<1><<<AGG_BLKS, 256>>>(x, p_agg);
    k_mma<128, true, true, true, false, false><<<dim3(MT, 2), 256>>>(
        p_agg, IN_F, IN_F, wbh + 0,     wbl + 0,     IN_F,
        x,     IN_F, IN_F, wbh + 32768, wbl + 32768, IN_F,
        bl0, nullptr, 0, p_h, HID_F, HID_F, nullptr, NN);

    // layer 1: pre -> hout, relu -> g_h2
    k_agg_vec<2><<<AGG_BLKS, 256>>>(p_h, p_agg);
    k_mma<128, true, true, true, true, false><<<dim3(MT, 2), 256>>>(
        p_agg, HID_F, HID_F, wbh + 65536,  wbl + 65536,  HID_F,
        p_h,   HID_F, HID_F, wbh + 131072, wbl + 131072, HID_F,
        bl1, nullptr, 0, p_h2, HID_F, HID_F, hout, NN);

    // layer 2: t2 = h2 @ Wl2 (N padded to 64, stride 48)
    k_mma<64, false, false, false, false, false><<<dim3(MT, 1), 256>>>(
        p_h2, HID_F, HID_F, wbh + 196608, wbl + 196608, HID_F,
        nullptr, 0, 0, nullptr, nullptr, 0,
        nullptr, nullptr, 0, p_t2, T2S, T2S, nullptr, NN);
    k_agg47<<<AGG_BLKS, 256>>>(p_t2, p_agg);
    // out = h2 @ Wr2 + bl2 + agg2
    k_mma<64, false, true, false, false, true><<<dim3(MT, 1), 256>>>(
        p_h2, HID_F, HID_F, wbh + 212992, wbl + 212992, HID_F,
        nullptr, 0, 0, nullptr, nullptr, 0,
        bl2, p_agg, T2S, out, OUT_F, OUT_F, nullptr, NN);
}